// round 1
// baseline (speedup 1.0000x reference)
#include <cuda_runtime.h>
#include <math.h>

#define D 512
#define K 5
#define THREADS 256
#define BLOCKS 1184   // 148 SMs * 8

__global__ __launch_bounds__(THREADS) void lfr_fused_kernel(
    const float* __restrict__ x,          // (N, D)
    const float* __restrict__ alpha,      // (D,)
    const float* __restrict__ w,          // (K,)
    const float* __restrict__ centroids,  // (K, D)
    float* __restrict__ out_map,          // (N, K)
    float* __restrict__ out_rec,          // (N, D)
    float* __restrict__ out_pred,         // (N,)
    int n_rows)
{
    __shared__ float s_c[K * D];      // 10 KB
    __shared__ float s_alpha[D];      // 2 KB
    __shared__ float s_sigw[K];

    const int tid = threadIdx.x;

    // Stage centroids + alpha + sigmoid(w) into shared (L2-resident source)
    for (int i = tid; i < K * D; i += THREADS) s_c[i] = centroids[i];
    for (int i = tid; i < D; i += THREADS)     s_alpha[i] = alpha[i];
    if (tid < K)                               s_sigw[tid] = 1.0f / (1.0f + __expf(-w[tid]));
    __syncthreads();

    const int lane        = tid & 31;
    const int warp_global = (blockIdx.x * THREADS + tid) >> 5;
    const int nwarps      = (BLOCKS * THREADS) >> 5;

    const float4* s_c4 = reinterpret_cast<const float4*>(s_c);
    const float4* s_a4 = reinterpret_cast<const float4*>(s_alpha);

    for (int row = warp_global; row < n_rows; row += nwarps) {
        const float4* xr = reinterpret_cast<const float4*>(x + (size_t)row * D);

        float dist[K];
        #pragma unroll
        for (int k = 0; k < K; k++) dist[k] = 0.0f;

        // Each lane: 4 float4 chunks, coalesced (lane + j*32)
        #pragma unroll
        for (int j = 0; j < 4; j++) {
            const int idx = lane + j * 32;       // float4 index; d = idx*4
            const float4 v = xr[idx];
            const float4 a = s_a4[idx];
            #pragma unroll
            for (int k = 0; k < K; k++) {
                const float4 c = s_c4[k * (D / 4) + idx];
                float d0 = v.x - c.x;
                float d1 = v.y - c.y;
                float d2 = v.z - c.z;
                float d3 = v.w - c.w;
                dist[k] += a.x * d0 * d0 + a.y * d1 * d1 + a.z * d2 * d2 + a.w * d3 * d3;
            }
        }

        // Warp tree-reduce the 5 distances (result replicated in all lanes)
        #pragma unroll
        for (int k = 0; k < K; k++) {
            #pragma unroll
            for (int off = 16; off > 0; off >>= 1)
                dist[k] += __shfl_xor_sync(0xffffffffu, dist[k], off);
        }

        // Softmax over K=5 (replicated per-lane, registers only)
        float m = dist[0];
        #pragma unroll
        for (int k = 1; k < K; k++) m = fmaxf(m, dist[k]);
        float e[K];
        float s = 0.0f;
        #pragma unroll
        for (int k = 0; k < K; k++) { e[k] = __expf(dist[k] - m); s += e[k]; }
        const float inv = 1.0f / s;
        float mp[K];
        #pragma unroll
        for (int k = 0; k < K; k++) mp[k] = e[k] * inv;

        // mapping: lanes 0..4 write one value each
        if (lane < K) out_map[(size_t)row * K + lane] = mp[lane];

        // pred: lane 0
        if (lane == 0) {
            float p = 0.0f;
            #pragma unroll
            for (int k = 0; k < K; k++) p += mp[k] * s_sigw[k];
            out_pred[row] = p;
        }

        // reconstructed = mapping @ centroids, each lane writes its 16 elems
        float4* orow = reinterpret_cast<float4*>(out_rec + (size_t)row * D);
        #pragma unroll
        for (int j = 0; j < 4; j++) {
            const int idx = lane + j * 32;
            float4 r = make_float4(0.f, 0.f, 0.f, 0.f);
            #pragma unroll
            for (int k = 0; k < K; k++) {
                const float4 c = s_c4[k * (D / 4) + idx];
                r.x += mp[k] * c.x;
                r.y += mp[k] * c.y;
                r.z += mp[k] * c.z;
                r.w += mp[k] * c.w;
            }
            orow[idx] = r;
        }
    }
}

extern "C" void kernel_launch(void* const* d_in, const int* in_sizes, int n_in,
                              void* d_out, int out_size) {
    // metadata order: x, is_protected (unused), alpha_p, classif_w, centroids
    const float* x     = (const float*)d_in[0];
    const float* alpha = (const float*)d_in[2];
    const float* w     = (const float*)d_in[3];
    const float* cent  = (const float*)d_in[4];

    const int n_rows = in_sizes[0] / D;   // 65536

    float* out      = (float*)d_out;
    float* out_map  = out;                              // N*K
    float* out_rec  = out + (size_t)n_rows * K;         // N*D
    float* out_pred = out_rec + (size_t)n_rows * D;     // N

    lfr_fused_kernel<<<BLOCKS, THREADS>>>(x, alpha, w, cent,
                                          out_map, out_rec, out_pred, n_rows);
}